// round 3
// baseline (speedup 1.0000x reference)
#include <cuda_runtime.h>

#define C_CHUNKS 16
#define NCW      2048
#define SUB      64
#define DIM      1024
#define TM       128
#define TN       128

typedef unsigned long long ull;

// scratch: per-codeword squared norms (16*2048 floats = 128KB)
__device__ float g_cbsq[C_CHUNKS * NCW];

// packed f32x2 fma: d.lo = a.lo*b.lo + c.lo ; d.hi = a.hi*b.hi + c.hi
__device__ __forceinline__ ull fma2(ull a, ull b, ull c) {
    ull d;
    asm("fma.rn.f32x2 %0, %1, %2, %3;" : "=l"(d) : "l"(a), "l"(b), "l"(c));
    return d;
}
__device__ __forceinline__ ull dup2(float v) {
    ull d;
    asm("mov.b64 %0, {%1, %1};" : "=l"(d) : "f"(v));
    return d;
}
__device__ __forceinline__ void unpack2(ull v, float& lo, float& hi) {
    asm("mov.b64 {%0, %1}, %2;" : "=f"(lo), "=f"(hi) : "l"(v));
}

// ---------------------------------------------------------------------------
// Kernel 0: codeword squared norms. One warp per codeword, coalesced float2.
// ---------------------------------------------------------------------------
__global__ void cbsq_kernel(const float* __restrict__ cb) {
    int w = (blockIdx.x * blockDim.x + threadIdx.x) >> 5;
    int lane = threadIdx.x & 31;
    if (w >= C_CHUNKS * NCW) return;
    const float2* p = reinterpret_cast<const float2*>(cb + (size_t)w * SUB);
    float2 v = p[lane];
    float s = v.x * v.x + v.y * v.y;
    #pragma unroll
    for (int o = 16; o > 0; o >>= 1) s += __shfl_xor_sync(0xffffffffu, s, o);
    if (lane == 0) g_cbsq[w] = s;
}

// ---------------------------------------------------------------------------
// Kernel 1: fused dots-GEMM + argmin + gather, packed f32x2 mainloop.
// Accumulators pack adjacent codeword columns (j, j+1) into one f32x2 pair;
// B pairs come packed for free from the float4/ulonglong2 LDS, A is
// half-duplicated on the (idle) ALU pipe. Exact fp32 arithmetic per lane.
// ---------------------------------------------------------------------------
__global__ __launch_bounds__(256, 2)
void vq_kernel(const float* __restrict__ x, const float* __restrict__ cb,
               float* __restrict__ out) {
    extern __shared__ float sm[];
    float* sA   = sm;                      // [SUB][TM]  x tile, k-major
    float* sB   = sm + SUB * TM;           // [SUB][TN]  codeword tile, k-major, permuted cols
    float* sXsq = sm + 2 * SUB * TM;       // [TM]
    int*   sIdx = reinterpret_cast<int*>(sm + 2 * SUB * TM + TM);  // [TM]

    const int tid   = threadIdx.x;
    const int chunk = blockIdx.y;
    const int t0    = blockIdx.x * TM;

    const float* cbc = cb + (size_t)chunk * NCW * SUB;
    const float* cqc = g_cbsq + chunk * NCW;

    // ---- load x tile transposed into sA, compute per-token |x|^2 ----
    {
        const int r = tid >> 1, h = tid & 1;
        const float4* xp = reinterpret_cast<const float4*>(
            x + (size_t)(t0 + r) * DIM + chunk * SUB + h * 32);
        float ssq = 0.f;
        #pragma unroll
        for (int q = 0; q < 8; q++) {
            float4 v = xp[q];
            int k = h * 32 + q * 4;
            sA[(k + 0) * TM + r] = v.x;
            sA[(k + 1) * TM + r] = v.y;
            sA[(k + 2) * TM + r] = v.z;
            sA[(k + 3) * TM + r] = v.w;
            ssq += v.x * v.x;
            ssq += v.y * v.y;
            ssq += v.z * v.z;
            ssq += v.w * v.w;
        }
        ssq += __shfl_xor_sync(0xffffffffu, ssq, 1);
        if (h == 0) sXsq[r] = ssq;
    }
    __syncthreads();

    const int ty = tid >> 4, tx = tid & 15;

    // hoist the 8 xsq values this thread needs
    float xq[8];
    #pragma unroll
    for (int i = 0; i < 8; i++) xq[i] = sXsq[ty * 8 + i];

    float minv[8];
    int   mini[8];
    #pragma unroll
    for (int i = 0; i < 8; i++) { minv[i] = 3.4028235e38f; mini[i] = 0; }

    for (int n0 = 0; n0 < NCW; n0 += TN) {
        __syncthreads();   // protect sB reuse from previous iteration's readers
        {
            // Store codeword r's k-values at permuted column m so that the
            // inner-loop 16B reads (tx*4 and 64+tx*4) are conflict-free.
            // Inverse map: column tx*4+q      <-> codeword n0 + tx*8 + q
            //              column 64+tx*4+q   <-> codeword n0 + tx*8 + 4 + q
            const int r = tid >> 1, h = tid & 1;
            const int m = ((r & 4) << 4) | ((r >> 3) << 2) | (r & 3);
            const float4* cp = reinterpret_cast<const float4*>(
                cbc + (size_t)(n0 + r) * SUB + h * 32);
            #pragma unroll
            for (int q = 0; q < 8; q++) {
                float4 v = cp[q];
                int k = h * 32 + q * 4;
                sB[(k + 0) * TN + m] = v.x;
                sB[(k + 1) * TN + m] = v.y;
                sB[(k + 2) * TN + m] = v.z;
                sB[(k + 3) * TN + m] = v.w;
            }
        }
        __syncthreads();

        // acc2[i][p] packs (j=2p, j=2p+1) for row i
        ull acc2[8][4];
        #pragma unroll
        for (int i = 0; i < 8; i++)
            #pragma unroll
            for (int p = 0; p < 4; p++) acc2[i][p] = 0ull;

        #pragma unroll 4
        for (int k = 0; k < SUB; k++) {
            float4 a0 = *reinterpret_cast<const float4*>(&sA[k * TM + ty * 8]);
            float4 a1 = *reinterpret_cast<const float4*>(&sA[k * TM + ty * 8 + 4]);
            ulonglong2 b0 = *reinterpret_cast<const ulonglong2*>(&sB[k * TN + tx * 4]);
            ulonglong2 b1 = *reinterpret_cast<const ulonglong2*>(&sB[k * TN + 64 + tx * 4]);
            ull rb2[4] = {b0.x, b0.y, b1.x, b1.y};
            ull ra2[8];
            ra2[0] = dup2(a0.x); ra2[1] = dup2(a0.y);
            ra2[2] = dup2(a0.z); ra2[3] = dup2(a0.w);
            ra2[4] = dup2(a1.x); ra2[5] = dup2(a1.y);
            ra2[6] = dup2(a1.z); ra2[7] = dup2(a1.w);
            #pragma unroll
            for (int i = 0; i < 8; i++)
                #pragma unroll
                for (int p = 0; p < 4; p++)
                    acc2[i][p] = fma2(ra2[i], rb2[p], acc2[i][p]);
        }

        // d2 = xsq - 2*dot + cbsq ; running argmin (n ascending, strict <)
        #pragma unroll
        for (int p = 0; p < 4; p++) {
            int n = n0 + tx * 8 + 2 * p;
            float cq0 = __ldg(&cqc[n]);
            float cq1 = __ldg(&cqc[n + 1]);
            #pragma unroll
            for (int i = 0; i < 8; i++) {
                float d0, d1;
                unpack2(acc2[i][p], d0, d1);
                float d20 = fmaf(-2.f, d0, xq[i]) + cq0;
                float d21 = fmaf(-2.f, d1, xq[i]) + cq1;
                if (d20 < minv[i]) { minv[i] = d20; mini[i] = n; }
                if (d21 < minv[i]) { minv[i] = d21; mini[i] = n + 1; }
            }
        }
    }

    // ---- cross-thread argmin reduction (overlay on sB, padded stride 17) ----
    __syncthreads();
    float* redv = sB;
    int*   redi = reinterpret_cast<int*>(sB + TM * 17);
    #pragma unroll
    for (int i = 0; i < 8; i++) {
        int row = ty * 8 + i;
        redv[row * 17 + tx] = minv[i];
        redi[row * 17 + tx] = mini[i];
    }
    __syncthreads();
    if (tid < TM) {
        float bv = redv[tid * 17];
        int   bi = redi[tid * 17];
        #pragma unroll
        for (int t = 1; t < 16; t++) {
            float v  = redv[tid * 17 + t];
            int   ii = redi[tid * 17 + t];
            if (v < bv || (v == bv && ii < bi)) { bv = v; bi = ii; }
        }
        sIdx[tid] = bi;
    }
    __syncthreads();

    // ---- gather winning codewords straight to output (K == 1) ----
    {
        const int r = tid >> 1, h = tid & 1;
        const int idx = sIdx[r];
        const float4* src = reinterpret_cast<const float4*>(
            cbc + (size_t)idx * SUB + h * 32);
        float4* dst = reinterpret_cast<float4*>(
            out + (size_t)(t0 + r) * DIM + chunk * SUB + h * 32);
        #pragma unroll
        for (int q = 0; q < 8; q++) dst[q] = src[q];
    }
}

extern "C" void kernel_launch(void* const* d_in, const int* in_sizes, int n_in,
                              void* d_out, int out_size) {
    const float* x  = (const float*)d_in[0];   // (4, 2048, 1024) fp32
    const float* cb = (const float*)d_in[1];   // (16, 2048, 64) fp32
    float* out = (float*)d_out;

    const int tokens = in_sizes[0] / DIM;      // 8192

    // Kernel 0: codeword norms (one warp per codeword)
    int n_warps = C_CHUNKS * NCW;
    cbsq_kernel<<<(n_warps * 32 + 255) / 256, 256>>>(cb);

    // Kernel 1: fused search + gather
    size_t smem = (size_t)(2 * SUB * TM + TM) * sizeof(float) + TM * sizeof(int);
    cudaFuncSetAttribute(vq_kernel,
                         cudaFuncAttributeMaxDynamicSharedMemorySize, (int)smem);
    dim3 grid(tokens / TM, C_CHUNKS);
    vq_kernel<<<grid, 256, smem>>>(x, cb, out);
}

// round 6
// speedup vs baseline: 1.4777x; 1.4777x over previous
#include <cuda_runtime.h>
#include <cuda_fp16.h>
#include <stdint.h>

#define C_CHUNKS 16
#define NCW      2048
#define SUB      64
#define DIM      1024
#define TM       128
#define BT       128            // codewords per B tile
#define NBT      (NCW / BT)     // 16
#define TAU      0.5f

// smem offsets (bytes); row stride 72 halves = 144B (LDSM conflict-free)
#define SM_A     0              // 128 x 72 halves = 18432
#define SM_B     18432          // 2 x 18432 = 36864
#define SM_BIAS  55296          // 2 x 128 f32 = 1024
#define SM_XSQ   56320          // 128 f32
#define SM_MAX   56832          // 64 x 128 f32 = 32768
#define SM_TOTAL 89600
// overlays on SM_B after mainloop:
#define SM_WL    SM_B           // 8192 x u32 = 32768 (max possible items)
#define SM_BEST  (SM_B + 32768) // 128 x u64
#define SM_WCNT  (SM_B + 33800)

typedef unsigned long long ull;

__device__ float g_cbsq[C_CHUNKS * NCW];
__device__ float g_bias[C_CHUNKS * NCW];
__device__ uint4 g_bimg[C_CHUNKS * NCW * 8];   // fp16 codebook, [row][64] halves

// ---------------------------------------------------------------------------
__device__ __forceinline__ uint32_t smem_u32(const void* p) {
    uint32_t a;
    asm("{ .reg .u64 t; cvta.to.shared.u64 t, %1; cvt.u32.u64 %0, t; }"
        : "=r"(a) : "l"(p));
    return a;
}
__device__ __forceinline__ void ldsm4(uint32_t& r0, uint32_t& r1, uint32_t& r2,
                                      uint32_t& r3, uint32_t a) {
    asm volatile("ldmatrix.sync.aligned.m8n8.x4.shared.b16 {%0,%1,%2,%3}, [%4];"
                 : "=r"(r0), "=r"(r1), "=r"(r2), "=r"(r3) : "r"(a));
}
__device__ __forceinline__ void mma16816(float* d, const uint32_t* a,
                                         uint32_t b0, uint32_t b1) {
    asm volatile(
        "mma.sync.aligned.m16n8k16.row.col.f32.f16.f16.f32 "
        "{%0,%1,%2,%3}, {%4,%5,%6,%7}, {%8,%9}, {%0,%1,%2,%3};"
        : "+f"(d[0]), "+f"(d[1]), "+f"(d[2]), "+f"(d[3])
        : "r"(a[0]), "r"(a[1]), "r"(a[2]), "r"(a[3]), "r"(b0), "r"(b1));
}
__device__ __forceinline__ uint32_t ord_f32(float f) {
    uint32_t u = __float_as_uint(f);
    return (u & 0x80000000u) ? ~u : (u | 0x80000000u);
}

// ---------------------------------------------------------------------------
// prep: fp16 codebook image (row-contiguous k) + cbsq + bias
// ---------------------------------------------------------------------------
__global__ void prep_kernel(const float* __restrict__ cb) {
    int n = blockIdx.x * 256 + threadIdx.x;          // 0..32767
    const float4* cp = reinterpret_cast<const float4*>(cb + (size_t)n * SUB);
    uint4 outv[8];
    uint32_t* ow = reinterpret_cast<uint32_t*>(outv);
    float ssq = 0.f;
    #pragma unroll
    for (int q = 0; q < 16; q++) {
        float4 v = cp[q];
        __half2 h0 = __floats2half2_rn(v.x, v.y);
        __half2 h1 = __floats2half2_rn(v.z, v.w);
        ow[q * 2]     = *reinterpret_cast<uint32_t*>(&h0);
        ow[q * 2 + 1] = *reinterpret_cast<uint32_t*>(&h1);
        ssq = fmaf(v.x, v.x, ssq); ssq = fmaf(v.y, v.y, ssq);
        ssq = fmaf(v.z, v.z, ssq); ssq = fmaf(v.w, v.w, ssq);
    }
    uint4* dst = g_bimg + (size_t)n * 8;
    #pragma unroll
    for (int j = 0; j < 8; j++) dst[j] = outv[j];
    g_cbsq[n] = ssq;
    g_bias[n] = -0.5f * ssq;
}

// ---------------------------------------------------------------------------
// main: HMMA fp16 filter + per-32-codeword subtile max + exact fp32 rescue
// grid (64, 16), 256 threads (8 warps, warp w owns token rows [16w,16w+16))
// ---------------------------------------------------------------------------
__global__ __launch_bounds__(256, 2)
void vq_kernel(const float* __restrict__ x, const float* __restrict__ cb,
               float* __restrict__ out) {
    extern __shared__ char sm[];
    const uint32_t smb = smem_u32(sm);
    const int tid = threadIdx.x, w = tid >> 5, lane = tid & 31;
    const int chunk = blockIdx.y;
    const int t0 = blockIdx.x * TM;
    const float* cbc = cb + (size_t)chunk * NCW * SUB;

    float* sBias = reinterpret_cast<float*>(sm + SM_BIAS);
    float* sXsq  = reinterpret_cast<float*>(sm + SM_XSQ);
    float* sMax  = reinterpret_cast<float*>(sm + SM_MAX);

    // ---- build fp16 A tile + exact xsq (same arithmetic/order as R1) ----
    {
        const int r = tid >> 1, h = tid & 1;
        const float4* xp = reinterpret_cast<const float4*>(
            x + (size_t)(t0 + r) * DIM + chunk * SUB + h * 32);
        __half* arow = reinterpret_cast<__half*>(sm + SM_A + r * 144 + h * 64);
        float ssq = 0.f;
        #pragma unroll
        for (int q = 0; q < 8; q++) {
            float4 v = xp[q];
            __half2* dh = reinterpret_cast<__half2*>(arow + q * 4);
            dh[0] = __floats2half2_rn(v.x, v.y);
            dh[1] = __floats2half2_rn(v.z, v.w);
            ssq = fmaf(v.x, v.x, ssq); ssq = fmaf(v.y, v.y, ssq);
            ssq = fmaf(v.z, v.z, ssq); ssq = fmaf(v.w, v.w, ssq);
        }
        ssq += __shfl_xor_sync(0xffffffffu, ssq, 1);
        if (h == 0) sXsq[r] = ssq;
    }
    // ---- copy B tile 0 + bias 0 ----
    {
        const uint4* src = g_bimg + (size_t)chunk * NCW * 8;
        #pragma unroll
        for (int r = 0; r < 4; r++) {
            int idx = r * 256 + tid, n = idx >> 3, kq = idx & 7;
            *reinterpret_cast<uint4*>(sm + SM_B + n * 144 + kq * 16) = src[idx];
        }
        if (tid < 128) sBias[tid] = g_bias[chunk * NCW + tid];
    }
    __syncthreads();

    // ---- A fragments (held in registers for the whole kernel) ----
    uint32_t aF[4][4];
    {
        const int aRow = ((lane >> 3) & 1) * 8 + (lane & 7);
        const int aK8  = lane >> 4;
        uint32_t abase = smb + SM_A + (w * 16 + aRow) * 144 + aK8 * 16;
        #pragma unroll
        for (int kt = 0; kt < 4; kt++)
            ldsm4(aF[kt][0], aF[kt][1], aF[kt][2], aF[kt][3], abase + kt * 32);
    }

    const int bRow = ((lane >> 3) & 1) * 8 + (lane & 7);
    const uint32_t laneOffB = bRow * 144 + (lane >> 4) * 16;
    const int gid = lane >> 2, tidg = lane & 3;

    // ---- mainloop over 16 B tiles, double-buffered ----
    for (int t = 0; t < NBT; t++) {
        const int buf = t & 1;
        uint4 pf[4]; float pfb = 0.f;
        if (t + 1 < NBT) {
            const uint4* src = g_bimg + ((size_t)chunk * NCW + (t + 1) * BT) * 8;
            #pragma unroll
            for (int r = 0; r < 4; r++) pf[r] = src[r * 256 + tid];
            if (tid < 128) pfb = g_bias[chunk * NCW + (t + 1) * BT + tid];
        }

        const uint32_t bbase = smb + SM_B + buf * 18432 + laneOffB;
        const float* biasb = sBias + buf * 128;

        #pragma unroll
        for (int s = 0; s < 4; s++) {
            float d[4][4];
            #pragma unroll
            for (int j = 0; j < 4; j++) {
                float2 bp = *reinterpret_cast<const float2*>(
                    biasb + s * 32 + j * 8 + tidg * 2);
                d[j][0] = bp.x; d[j][1] = bp.y; d[j][2] = bp.x; d[j][3] = bp.y;
            }
            #pragma unroll
            for (int kt = 0; kt < 4; kt++) {
                uint32_t b0, b1, b2, b3, b4, b5, b6, b7;
                uint32_t ad = bbase + s * (32 * 144) + kt * 32;
                ldsm4(b0, b1, b2, b3, ad);
                ldsm4(b4, b5, b6, b7, ad + 16 * 144);
                // ldmatrix.x4 order: {n0-7/klo, n8-15/klo, n0-7/khi, n8-15/khi}
                // MMA B operand needs (k-lo, k-hi) of the SAME n-8 group:
                mma16816(d[0], aF[kt], b0, b2);   // n  0- 7
                mma16816(d[1], aF[kt], b1, b3);   // n  8-15
                mma16816(d[2], aF[kt], b4, b6);   // n 16-23
                mma16816(d[3], aF[kt], b5, b7);   // n 24-31
            }
            // subtile max per token row (row gid and gid+8)
            float r0m = fmaxf(fmaxf(d[0][0], d[0][1]), fmaxf(d[1][0], d[1][1]));
            r0m = fmaxf(r0m, fmaxf(fmaxf(d[2][0], d[2][1]), fmaxf(d[3][0], d[3][1])));
            float r1m = fmaxf(fmaxf(d[0][2], d[0][3]), fmaxf(d[1][2], d[1][3]));
            r1m = fmaxf(r1m, fmaxf(fmaxf(d[2][2], d[2][3]), fmaxf(d[3][2], d[3][3])));
            r0m = fmaxf(r0m, __shfl_xor_sync(0xffffffffu, r0m, 1));
            r0m = fmaxf(r0m, __shfl_xor_sync(0xffffffffu, r0m, 2));
            r1m = fmaxf(r1m, __shfl_xor_sync(0xffffffffu, r1m, 1));
            r1m = fmaxf(r1m, __shfl_xor_sync(0xffffffffu, r1m, 2));
            if (tidg == 0) {
                const int sg = t * 4 + s;
                sMax[sg * 128 + w * 16 + gid]     = r0m;
                sMax[sg * 128 + w * 16 + gid + 8] = r1m;
            }
        }

        if (t + 1 < NBT) {
            #pragma unroll
            for (int r = 0; r < 4; r++) {
                int idx = r * 256 + tid, n = idx >> 3, kq = idx & 7;
                *reinterpret_cast<uint4*>(
                    sm + SM_B + (buf ^ 1) * 18432 + n * 144 + kq * 16) = pf[r];
            }
            if (tid < 128) sBias[(buf ^ 1) * 128 + tid] = pfb;
        }
        __syncthreads();
    }

    // ---- build rescue worklist (overlay on sB region) ----
    uint32_t* wl   = reinterpret_cast<uint32_t*>(sm + SM_WL);
    ull*      sBest = reinterpret_cast<ull*>(sm + SM_BEST);
    uint32_t* wcnt = reinterpret_cast<uint32_t*>(sm + SM_WCNT);
    if (tid < 128) sBest[tid] = ~0ull;
    if (tid == 0) *wcnt = 0;
    __syncthreads();

    if (tid < 128) {
        float gm = -3.4028235e38f;
        #pragma unroll 8
        for (int s2 = 0; s2 < 64; s2++) gm = fmaxf(gm, sMax[s2 * 128 + tid]);
        const float thr = gm - TAU;
        for (int s2 = 0; s2 < 64; s2++)
            if (sMax[s2 * 128 + tid] >= thr) {
                uint32_t p = atomicAdd(wcnt, 1u);
                wl[p] = ((uint32_t)tid << 8) | (uint32_t)s2;
            }
    }
    __syncthreads();

    // ---- exact fp32 rescue (R1-identical arithmetic) ----
    const int cnt = *wcnt;
    const float* cqc = g_cbsq + chunk * NCW;
    for (int it = w; it < cnt; it += 8) {
        const uint32_t item = wl[it];
        const int tk = item >> 8, st = item & 255;
        const int n = st * 32 + lane;
        const float4* cp = reinterpret_cast<const float4*>(cbc + (size_t)n * SUB);
        const float4* xv = reinterpret_cast<const float4*>(
            x + (size_t)(t0 + tk) * DIM + chunk * SUB);
        float acc = 0.f;
        #pragma unroll
        for (int q = 0; q < 16; q++) {
            float4 c4 = __ldg(cp + q);
            float4 x4 = xv[q];
            acc = fmaf(c4.x, x4.x, acc);
            acc = fmaf(c4.y, x4.y, acc);
            acc = fmaf(c4.z, x4.z, acc);
            acc = fmaf(c4.w, x4.w, acc);
        }
        const float d2 = fmaf(-2.f, acc, sXsq[tk]) + __ldg(&cqc[n]);
        const ull key = ((ull)ord_f32(d2) << 32) | (uint32_t)n;
        atomicMin(&sBest[tk], key);
    }
    __syncthreads();

    // ---- gather winning codewords ----
    {
        const int r = tid >> 1, h = tid & 1;
        const uint32_t n = (uint32_t)(sBest[r] & 0xFFFFFFFFull);
        const float4* src = reinterpret_cast<const float4*>(
            cbc + (size_t)n * SUB + h * 32);
        float4* dst = reinterpret_cast<float4*>(
            out + (size_t)(t0 + r) * DIM + chunk * SUB + h * 32);
        #pragma unroll
        for (int q = 0; q < 8; q++) dst[q] = src[q];
    }
}

extern "C" void kernel_launch(void* const* d_in, const int* in_sizes, int n_in,
                              void* d_out, int out_size) {
    (void)n_in; (void)out_size;
    const float* x  = (const float*)d_in[0];   // (4,2048,1024) fp32
    const float* cb = (const float*)d_in[1];   // (16,2048,64) fp32
    float* out = (float*)d_out;
    const int tokens = in_sizes[0] / DIM;      // 8192

    cudaFuncSetAttribute(vq_kernel,
                         cudaFuncAttributeMaxDynamicSharedMemorySize, SM_TOTAL);

    prep_kernel<<<C_CHUNKS * NCW / 256, 256>>>(cb);
    dim3 grid(tokens / TM, C_CHUNKS);
    vq_kernel<<<grid, 256, SM_TOTAL>>>(x, cb, out);
}

// round 7
// speedup vs baseline: 1.7282x; 1.1695x over previous
#include <cuda_runtime.h>
#include <cuda_fp16.h>
#include <stdint.h>

#define C_CHUNKS 16
#define NCW      2048
#define SUB      64
#define DIM      1024
#define TM       128
#define BT       128            // codewords per B tile
#define NBT      (NCW / BT)     // 16
#define TAU      0.5f

// smem offsets (bytes); row stride 72 halves = 144B (LDSM conflict-free)
#define SM_A     0              // 128 x 72 halves = 18432
#define SM_B     18432          // 2 x 18432 = 36864
#define SM_BIAS  55296          // 2 x 128 f32 = 1024
#define SM_XSQ   56320          // 128 f32
#define SM_MAX   56832          // 64 x 128 f32 = 32768
#define SM_TOTAL 89600
// overlays on SM_B after mainloop:
#define SM_WL    SM_B           // up to 8192 x u32
#define SM_BEST  (SM_B + 32768) // 128 x u64
#define SM_WCNT  (SM_B + 33800)

typedef unsigned long long ull;

__device__ float g_cbsq[C_CHUNKS * NCW];
__device__ float g_bias[C_CHUNKS * NCW];
__device__ uint4 g_bimg[C_CHUNKS * NCW * 8];   // fp16 codebook, [row][64] halves

// ---------------------------------------------------------------------------
__device__ __forceinline__ uint32_t smem_u32(const void* p) {
    uint32_t a;
    asm("{ .reg .u64 t; cvta.to.shared.u64 t, %1; cvt.u32.u64 %0, t; }"
        : "=r"(a) : "l"(p));
    return a;
}
__device__ __forceinline__ void ldsm4(uint32_t& r0, uint32_t& r1, uint32_t& r2,
                                      uint32_t& r3, uint32_t a) {
    asm volatile("ldmatrix.sync.aligned.m8n8.x4.shared.b16 {%0,%1,%2,%3}, [%4];"
                 : "=r"(r0), "=r"(r1), "=r"(r2), "=r"(r3) : "r"(a));
}
__device__ __forceinline__ void mma16816(float* d, const uint32_t* a,
                                         uint32_t b0, uint32_t b1) {
    asm volatile(
        "mma.sync.aligned.m16n8k16.row.col.f32.f16.f16.f32 "
        "{%0,%1,%2,%3}, {%4,%5,%6,%7}, {%8,%9}, {%0,%1,%2,%3};"
        : "+f"(d[0]), "+f"(d[1]), "+f"(d[2]), "+f"(d[3])
        : "r"(a[0]), "r"(a[1]), "r"(a[2]), "r"(a[3]), "r"(b0), "r"(b1));
}
__device__ __forceinline__ uint32_t ord_f32(float f) {
    uint32_t u = __float_as_uint(f);
    return (u & 0x80000000u) ? ~u : (u | 0x80000000u);
}

// ---------------------------------------------------------------------------
// prep: fp16 codebook image (row-contiguous k) + cbsq + bias
// ---------------------------------------------------------------------------
__global__ void prep_kernel(const float* __restrict__ cb) {
    int n = blockIdx.x * 256 + threadIdx.x;          // 0..32767
    const float4* cp = reinterpret_cast<const float4*>(cb + (size_t)n * SUB);
    uint4 outv[8];
    uint32_t* ow = reinterpret_cast<uint32_t*>(outv);
    float ssq = 0.f;
    #pragma unroll
    for (int q = 0; q < 16; q++) {
        float4 v = cp[q];
        __half2 h0 = __floats2half2_rn(v.x, v.y);
        __half2 h1 = __floats2half2_rn(v.z, v.w);
        ow[q * 2]     = *reinterpret_cast<uint32_t*>(&h0);
        ow[q * 2 + 1] = *reinterpret_cast<uint32_t*>(&h1);
        ssq = fmaf(v.x, v.x, ssq); ssq = fmaf(v.y, v.y, ssq);
        ssq = fmaf(v.z, v.z, ssq); ssq = fmaf(v.w, v.w, ssq);
    }
    uint4* dst = g_bimg + (size_t)n * 8;
    #pragma unroll
    for (int j = 0; j < 8; j++) dst[j] = outv[j];
    g_cbsq[n] = ssq;
    g_bias[n] = -0.5f * ssq;
}

// ---------------------------------------------------------------------------
// main: HMMA fp16 filter + subtile max + exact fp32 rescue
// grid (64, 16), 256 threads. Warp w: M-group (w&3)*32 rows, N-half (w>>2).
// Each B fragment feeds 2 MMAs (two m16 blocks) -> LDSM traffic halved vs R6.
// ---------------------------------------------------------------------------
__global__ __launch_bounds__(256, 2)
void vq_kernel(const float* __restrict__ x, const float* __restrict__ cb,
               float* __restrict__ out) {
    extern __shared__ char sm[];
    const uint32_t smb = smem_u32(sm);
    const int tid = threadIdx.x, w = tid >> 5, lane = tid & 31;
    const int chunk = blockIdx.y;
    const int t0 = blockIdx.x * TM;
    const float* cbc = cb + (size_t)chunk * NCW * SUB;

    float* sBias = reinterpret_cast<float*>(sm + SM_BIAS);
    float* sXsq  = reinterpret_cast<float*>(sm + SM_XSQ);
    float* sMax  = reinterpret_cast<float*>(sm + SM_MAX);

    // ---- build fp16 A tile + exact xsq (same arithmetic/order as R1) ----
    {
        const int r = tid >> 1, h = tid & 1;
        const float4* xp = reinterpret_cast<const float4*>(
            x + (size_t)(t0 + r) * DIM + chunk * SUB + h * 32);
        __half* arow = reinterpret_cast<__half*>(sm + SM_A + r * 144 + h * 64);
        float ssq = 0.f;
        #pragma unroll
        for (int q = 0; q < 8; q++) {
            float4 v = xp[q];
            __half2* dh = reinterpret_cast<__half2*>(arow + q * 4);
            dh[0] = __floats2half2_rn(v.x, v.y);
            dh[1] = __floats2half2_rn(v.z, v.w);
            ssq = fmaf(v.x, v.x, ssq); ssq = fmaf(v.y, v.y, ssq);
            ssq = fmaf(v.z, v.z, ssq); ssq = fmaf(v.w, v.w, ssq);
        }
        ssq += __shfl_xor_sync(0xffffffffu, ssq, 1);
        if (h == 0) sXsq[r] = ssq;
    }
    // ---- copy B tile 0 + bias 0 ----
    {
        const uint4* src = g_bimg + (size_t)chunk * NCW * 8;
        #pragma unroll
        for (int r = 0; r < 4; r++) {
            int idx = r * 256 + tid, n = idx >> 3, kq = idx & 7;
            *reinterpret_cast<uint4*>(sm + SM_B + n * 144 + kq * 16) = src[idx];
        }
        if (tid < 128) sBias[tid] = g_bias[chunk * NCW + tid];
    }
    __syncthreads();

    const int mg = w & 3;    // M group: token rows [mg*32, mg*32+32)
    const int ng = w >> 2;   // N half: subtiles s = 2*ng, 2*ng+1

    // ---- A fragments: 2 m16 blocks, held in registers all kernel ----
    uint32_t aF[2][4][4];
    {
        const int aRow = ((lane >> 3) & 1) * 8 + (lane & 7);
        const int aK8  = lane >> 4;
        #pragma unroll
        for (int mb = 0; mb < 2; mb++) {
            uint32_t abase = smb + SM_A + (mg * 32 + mb * 16 + aRow) * 144
                           + aK8 * 16;
            #pragma unroll
            for (int kt = 0; kt < 4; kt++)
                ldsm4(aF[mb][kt][0], aF[mb][kt][1], aF[mb][kt][2],
                      aF[mb][kt][3], abase + kt * 32);
        }
    }

    const int bRow = ((lane >> 3) & 1) * 8 + (lane & 7);
    const uint32_t laneOffB = bRow * 144 + (lane >> 4) * 16;
    const int gid = lane >> 2, tidg = lane & 3;

    // ---- mainloop over 16 B tiles, double-buffered ----
    for (int t = 0; t < NBT; t++) {
        const int buf = t & 1;
        uint4 pf[4]; float pfb = 0.f;
        if (t + 1 < NBT) {
            const uint4* src = g_bimg + ((size_t)chunk * NCW + (t + 1) * BT) * 8;
            #pragma unroll
            for (int r = 0; r < 4; r++) pf[r] = src[r * 256 + tid];
            if (tid < 128) pfb = g_bias[chunk * NCW + (t + 1) * BT + tid];
        }

        const uint32_t bbase = smb + SM_B + buf * 18432 + laneOffB;
        const float* biasb = sBias + buf * 128;

        #pragma unroll
        for (int ss = 0; ss < 2; ss++) {
            const int s = ng * 2 + ss;
            float d[2][4][4];
            #pragma unroll
            for (int j = 0; j < 4; j++) {
                float2 bp = *reinterpret_cast<const float2*>(
                    biasb + s * 32 + j * 8 + tidg * 2);
                #pragma unroll
                for (int mb = 0; mb < 2; mb++) {
                    d[mb][j][0] = bp.x; d[mb][j][1] = bp.y;
                    d[mb][j][2] = bp.x; d[mb][j][3] = bp.y;
                }
            }
            #pragma unroll
            for (int kt = 0; kt < 4; kt++) {
                uint32_t b0, b1, b2, b3, b4, b5, b6, b7;
                uint32_t ad = bbase + s * (32 * 144) + kt * 32;
                ldsm4(b0, b1, b2, b3, ad);
                ldsm4(b4, b5, b6, b7, ad + 16 * 144);
                // ldmatrix.x4 order: {n0-7/klo, n8-15/klo, n0-7/khi, n8-15/khi}
                #pragma unroll
                for (int mb = 0; mb < 2; mb++) {
                    mma16816(d[mb][0], aF[mb][kt], b0, b2);   // n  0- 7
                    mma16816(d[mb][1], aF[mb][kt], b1, b3);   // n  8-15
                    mma16816(d[mb][2], aF[mb][kt], b4, b6);   // n 16-23
                    mma16816(d[mb][3], aF[mb][kt], b5, b7);   // n 24-31
                }
            }
            // subtile max per token row
            #pragma unroll
            for (int mb = 0; mb < 2; mb++) {
                float r0m = fmaxf(fmaxf(d[mb][0][0], d[mb][0][1]),
                                  fmaxf(d[mb][1][0], d[mb][1][1]));
                r0m = fmaxf(r0m, fmaxf(fmaxf(d[mb][2][0], d[mb][2][1]),
                                       fmaxf(d[mb][3][0], d[mb][3][1])));
                float r1m = fmaxf(fmaxf(d[mb][0][2], d[mb][0][3]),
                                  fmaxf(d[mb][1][2], d[mb][1][3]));
                r1m = fmaxf(r1m, fmaxf(fmaxf(d[mb][2][2], d[mb][2][3]),
                                       fmaxf(d[mb][3][2], d[mb][3][3])));
                r0m = fmaxf(r0m, __shfl_xor_sync(0xffffffffu, r0m, 1));
                r0m = fmaxf(r0m, __shfl_xor_sync(0xffffffffu, r0m, 2));
                r1m = fmaxf(r1m, __shfl_xor_sync(0xffffffffu, r1m, 1));
                r1m = fmaxf(r1m, __shfl_xor_sync(0xffffffffu, r1m, 2));
                if (tidg == 0) {
                    const int sg  = t * 4 + s;
                    const int row = mg * 32 + mb * 16 + gid;
                    sMax[sg * 128 + row]     = r0m;
                    sMax[sg * 128 + row + 8] = r1m;
                }
            }
        }

        if (t + 1 < NBT) {
            #pragma unroll
            for (int r = 0; r < 4; r++) {
                int idx = r * 256 + tid, n = idx >> 3, kq = idx & 7;
                *reinterpret_cast<uint4*>(
                    sm + SM_B + (buf ^ 1) * 18432 + n * 144 + kq * 16) = pf[r];
            }
            if (tid < 128) sBias[(buf ^ 1) * 128 + tid] = pfb;
        }
        __syncthreads();
    }

    // ---- build rescue worklist (overlay on sB region) ----
    uint32_t* wl    = reinterpret_cast<uint32_t*>(sm + SM_WL);
    ull*      sBest = reinterpret_cast<ull*>(sm + SM_BEST);
    uint32_t* wcnt  = reinterpret_cast<uint32_t*>(sm + SM_WCNT);
    if (tid < 128) sBest[tid] = ~0ull;
    if (tid == 0) *wcnt = 0;
    __syncthreads();

    if (tid < 128) {
        float gm = -3.4028235e38f;
        #pragma unroll 8
        for (int s2 = 0; s2 < 64; s2++) gm = fmaxf(gm, sMax[s2 * 128 + tid]);
        const float thr = gm - TAU;
        for (int s2 = 0; s2 < 64; s2++)
            if (sMax[s2 * 128 + tid] >= thr) {
                uint32_t p = atomicAdd(wcnt, 1u);
                wl[p] = ((uint32_t)tid << 8) | (uint32_t)s2;
            }
    }
    __syncthreads();

    // ---- exact fp32 rescue (R1-identical arithmetic) ----
    const int cnt = *wcnt;
    const float* cqc = g_cbsq + chunk * NCW;
    for (int it = w; it < cnt; it += 8) {
        const uint32_t item = wl[it];
        const int tk = item >> 8, st = item & 255;
        const int n = st * 32 + lane;
        const float4* cp = reinterpret_cast<const float4*>(cbc + (size_t)n * SUB);
        const float4* xv = reinterpret_cast<const float4*>(
            x + (size_t)(t0 + tk) * DIM + chunk * SUB);
        float acc = 0.f;
        #pragma unroll
        for (int q = 0; q < 16; q++) {
            float4 c4 = __ldg(cp + q);
            float4 x4 = xv[q];
            acc = fmaf(c4.x, x4.x, acc);
            acc = fmaf(c4.y, x4.y, acc);
            acc = fmaf(c4.z, x4.z, acc);
            acc = fmaf(c4.w, x4.w, acc);
        }
        const float d2 = fmaf(-2.f, acc, sXsq[tk]) + __ldg(&cqc[n]);
        const ull key = ((ull)ord_f32(d2) << 32) | (uint32_t)n;
        atomicMin(&sBest[tk], key);
    }
    __syncthreads();

    // ---- gather winning codewords ----
    {
        const int r = tid >> 1, h = tid & 1;
        const uint32_t n = (uint32_t)(sBest[r] & 0xFFFFFFFFull);
        const float4* src = reinterpret_cast<const float4*>(
            cbc + (size_t)n * SUB + h * 32);
        float4* dst = reinterpret_cast<float4*>(
            out + (size_t)(t0 + r) * DIM + chunk * SUB + h * 32);
        #pragma unroll
        for (int q = 0; q < 8; q++) dst[q] = src[q];
    }
}

extern "C" void kernel_launch(void* const* d_in, const int* in_sizes, int n_in,
                              void* d_out, int out_size) {
    (void)n_in; (void)out_size;
    const float* x  = (const float*)d_in[0];   // (4,2048,1024) fp32
    const float* cb = (const float*)d_in[1];   // (16,2048,64) fp32
    float* out = (float*)d_out;
    const int tokens = in_sizes[0] / DIM;      // 8192

    cudaFuncSetAttribute(vq_kernel,
                         cudaFuncAttributeMaxDynamicSharedMemorySize, SM_TOTAL);

    prep_kernel<<<C_CHUNKS * NCW / 256, 256>>>(cb);
    dim3 grid(tokens / TM, C_CHUNKS);
    vq_kernel<<<grid, 256, SM_TOTAL>>>(x, cb, out);
}

// round 8
// speedup vs baseline: 2.9895x; 1.7298x over previous
#include <cuda_runtime.h>
#include <cuda_fp16.h>
#include <stdint.h>

#define C_CHUNKS 16
#define NCW      2048
#define SUB      64
#define DIM      1024
#define TM       128
#define BT       128            // codewords per B tile
#define NBT      (NCW / BT)     // 16

// smem offsets (bytes); B/A row stride 72 halves = 144B (LDSM conflict-free)
#define SM_A     0              // 128 x 144B = 18432
#define SM_B     18432          // 2 x 18432 = 36864
#define SM_BIAS  55296          // 2 x 128 f32 = 1024
#define SM_XSQ   56320          // 128 f32
#define SM_EPS   56832          // 128 f32 (per-token 2*eps threshold)
#define SM_MAX   57344          // 64 x 128 f32 = 32768
#define SM_TOP   90112          // 3 x 256 f32 = 3072 (t1v/t2v/t1i x [ng][row])
#define SM_TOTAL 93184
// overlays on SM_B after mainloop:
#define SM_WL    SM_B           // worst case 8192 x u32 = 32768
#define SM_BEST  (SM_B + 32768) // 128 x u64
#define SM_WCNT  (SM_B + 33800)

typedef unsigned long long ull;

__device__ float g_cbsq[C_CHUNKS * NCW];
__device__ float g_bias[C_CHUNKS * NCW];
__device__ float g_cmax[C_CHUNKS * SUB];       // per (chunk,k) max |c|
__device__ uint4 g_bimg[C_CHUNKS * NCW * 8];   // fp16 codebook, [row][64] halves

// ---------------------------------------------------------------------------
__device__ __forceinline__ uint32_t smem_u32(const void* p) {
    uint32_t a;
    asm("{ .reg .u64 t; cvta.to.shared.u64 t, %1; cvt.u32.u64 %0, t; }"
        : "=r"(a) : "l"(p));
    return a;
}
__device__ __forceinline__ void ldsm4(uint32_t& r0, uint32_t& r1, uint32_t& r2,
                                      uint32_t& r3, uint32_t a) {
    asm volatile("ldmatrix.sync.aligned.m8n8.x4.shared.b16 {%0,%1,%2,%3}, [%4];"
                 : "=r"(r0), "=r"(r1), "=r"(r2), "=r"(r3) : "r"(a));
}
__device__ __forceinline__ void mma16816(float* d, const uint32_t* a,
                                         uint32_t b0, uint32_t b1) {
    asm volatile(
        "mma.sync.aligned.m16n8k16.row.col.f32.f16.f16.f32 "
        "{%0,%1,%2,%3}, {%4,%5,%6,%7}, {%8,%9}, {%0,%1,%2,%3};"
        : "+f"(d[0]), "+f"(d[1]), "+f"(d[2]), "+f"(d[3])
        : "r"(a[0]), "r"(a[1]), "r"(a[2]), "r"(a[3]), "r"(b0), "r"(b1));
}
__device__ __forceinline__ void cp16(uint32_t dst, const void* src) {
    asm volatile("cp.async.cg.shared.global [%0], [%1], 16;"
                 :: "r"(dst), "l"(src));
}
__device__ __forceinline__ void cp4(uint32_t dst, const void* src) {
    asm volatile("cp.async.ca.shared.global [%0], [%1], 4;"
                 :: "r"(dst), "l"(src));
}
#define CP_COMMIT() asm volatile("cp.async.commit_group;" ::: "memory")
#define CP_WAIT0()  asm volatile("cp.async.wait_group 0;" ::: "memory")

__device__ __forceinline__ uint32_t ord_f32(float f) {
    uint32_t u = __float_as_uint(f);
    return (u & 0x80000000u) ? ~u : (u | 0x80000000u);
}
// top-2 update, select form
__device__ __forceinline__ void upd2(float& t1, int& ti, float& t2,
                                     float v, int n) {
    const bool g = v > t1;
    t2 = g ? t1 : fmaxf(t2, v);
    ti = g ? n : ti;
    t1 = g ? v : t1;
}

// ---------------------------------------------------------------------------
// prep: fp16 codebook image (row-contiguous k) + cbsq + bias
// ---------------------------------------------------------------------------
__global__ void prep_kernel(const float* __restrict__ cb) {
    int n = blockIdx.x * 256 + threadIdx.x;          // 0..32767
    const float4* cp = reinterpret_cast<const float4*>(cb + (size_t)n * SUB);
    uint4 outv[8];
    uint32_t* ow = reinterpret_cast<uint32_t*>(outv);
    float ssq = 0.f;
    #pragma unroll
    for (int q = 0; q < 16; q++) {
        float4 v = cp[q];
        __half2 h0 = __floats2half2_rn(v.x, v.y);
        __half2 h1 = __floats2half2_rn(v.z, v.w);
        ow[q * 2]     = *reinterpret_cast<uint32_t*>(&h0);
        ow[q * 2 + 1] = *reinterpret_cast<uint32_t*>(&h1);
        ssq = fmaf(v.x, v.x, ssq); ssq = fmaf(v.y, v.y, ssq);
        ssq = fmaf(v.z, v.z, ssq); ssq = fmaf(v.w, v.w, ssq);
    }
    uint4* dst = g_bimg + (size_t)n * 8;
    #pragma unroll
    for (int j = 0; j < 8; j++) dst[j] = outv[j];
    g_cbsq[n] = ssq;
    g_bias[n] = -0.5f * ssq;
}

// per-(chunk,k) max |c|, coalesced, no atomics
__global__ void cmax_kernel(const float* __restrict__ cb) {
    __shared__ float red[256];
    const int chunk = blockIdx.x;
    const int k = threadIdx.x & 63, part = threadIdx.x >> 6;
    const float* base = cb + (size_t)chunk * NCW * SUB;
    float m = 0.f;
    for (int r = part; r < NCW; r += 4)
        m = fmaxf(m, fabsf(base[(size_t)r * SUB + k]));
    red[threadIdx.x] = m;
    __syncthreads();
    if (threadIdx.x < 64) {
        m = fmaxf(fmaxf(red[threadIdx.x], red[threadIdx.x + 64]),
                  fmaxf(red[threadIdx.x + 128], red[threadIdx.x + 192]));
        g_cmax[chunk * 64 + threadIdx.x] = m;
    }
}

// ---------------------------------------------------------------------------
// main: HMMA fp16 filter + per-score top-2 gap proof + rare exact rescue
// grid (64, 16), 256 threads. Warp w: M-group (w&3)*32 rows, N-half (w>>2).
// ---------------------------------------------------------------------------
__global__ __launch_bounds__(256, 2)
void vq_kernel(const float* __restrict__ x, const float* __restrict__ cb,
               float* __restrict__ out) {
    extern __shared__ char sm[];
    const uint32_t smb = smem_u32(sm);
    const int tid = threadIdx.x, w = tid >> 5, lane = tid & 31;
    const int chunk = blockIdx.y;
    const int t0 = blockIdx.x * TM;
    const float* cbc = cb + (size_t)chunk * NCW * SUB;

    float* sBias = reinterpret_cast<float*>(sm + SM_BIAS);
    float* sXsq  = reinterpret_cast<float*>(sm + SM_XSQ);
    float* sEps  = reinterpret_cast<float*>(sm + SM_EPS);
    float* sMax  = reinterpret_cast<float*>(sm + SM_MAX);
    float* sT1   = reinterpret_cast<float*>(sm + SM_TOP);            // [2][128]
    float* sT2   = reinterpret_cast<float*>(sm + SM_TOP + 1024);     // [2][128]
    int*   sTI   = reinterpret_cast<int*>  (sm + SM_TOP + 2048);     // [2][128]

    // ---- build fp16 A tile + exact xsq + per-token error threshold ----
    {
        const int r = tid >> 1, h = tid & 1;
        const float4* xp = reinterpret_cast<const float4*>(
            x + (size_t)(t0 + r) * DIM + chunk * SUB + h * 32);
        const float4* cm4 = reinterpret_cast<const float4*>(
            g_cmax + chunk * 64 + h * 32);
        __half* arow = reinterpret_cast<__half*>(sm + SM_A + r * 144 + h * 64);
        float ssq = 0.f, sabs = 0.f;
        #pragma unroll
        for (int q = 0; q < 8; q++) {
            float4 v = xp[q];
            float4 cm = __ldg(cm4 + q);
            __half2* dh = reinterpret_cast<__half2*>(arow + q * 4);
            dh[0] = __floats2half2_rn(v.x, v.y);
            dh[1] = __floats2half2_rn(v.z, v.w);
            ssq = fmaf(v.x, v.x, ssq); ssq = fmaf(v.y, v.y, ssq);
            ssq = fmaf(v.z, v.z, ssq); ssq = fmaf(v.w, v.w, ssq);
            sabs = fmaf(fabsf(v.x), cm.x, sabs);
            sabs = fmaf(fabsf(v.y), cm.y, sabs);
            sabs = fmaf(fabsf(v.z), cm.z, sabs);
            sabs = fmaf(fabsf(v.w), cm.w, sabs);
        }
        ssq  += __shfl_xor_sync(0xffffffffu, ssq, 1);
        sabs += __shfl_xor_sync(0xffffffffu, sabs, 1);
        if (h == 0) {
            sXsq[r] = ssq;
            // 2*eps: fp16 rounding (2^-10 * S) + fp32 accum slack + abs slack
            sEps[r] = 2.f * (0.001f * sabs + 2e-5f * (sabs + 64.f) + 1e-4f);
        }
    }
    // ---- copy B tile 0 + bias 0 (plain) ----
    {
        const uint4* src = g_bimg + (size_t)chunk * NCW * 8;
        #pragma unroll
        for (int r = 0; r < 4; r++) {
            int idx = r * 256 + tid, n = idx >> 3, kq = idx & 7;
            *reinterpret_cast<uint4*>(sm + SM_B + n * 144 + kq * 16) = src[idx];
        }
        if (tid < 128) sBias[tid] = g_bias[chunk * NCW + tid];
    }
    __syncthreads();

    const int mg = w & 3;    // M group: token rows [mg*32, mg*32+32)
    const int ng = w >> 2;   // N half: subtiles s = 2*ng, 2*ng+1

    // ---- A fragments: 2 m16 blocks, registers for the whole kernel ----
    uint32_t aF[2][4][4];
    {
        const int aRow = ((lane >> 3) & 1) * 8 + (lane & 7);
        const int aK8  = lane >> 4;
        #pragma unroll
        for (int mb = 0; mb < 2; mb++) {
            uint32_t abase = smb + SM_A + (mg * 32 + mb * 16 + aRow) * 144
                           + aK8 * 16;
            #pragma unroll
            for (int kt = 0; kt < 4; kt++)
                ldsm4(aF[mb][kt][0], aF[mb][kt][1], aF[mb][kt][2],
                      aF[mb][kt][3], abase + kt * 32);
        }
    }

    const int bRow = ((lane >> 3) & 1) * 8 + (lane & 7);
    const uint32_t laneOffB = bRow * 144 + (lane >> 4) * 16;
    const int gid = lane >> 2, tidg = lane & 3;

    // per-lane top-2 trackers; slot = mb*2 + half (half1 = row+8)
    float t1v[4], t2v[4]; int t1i[4];
    #pragma unroll
    for (int i = 0; i < 4; i++) {
        t1v[i] = -3.4028235e38f; t2v[i] = -3.4028235e38f; t1i[i] = 0;
    }

    // ---- mainloop over 16 B tiles, double-buffered via cp.async ----
    for (int t = 0; t < NBT; t++) {
        const int buf = t & 1;
        if (t + 1 < NBT) {
            const uint4* src = g_bimg + ((size_t)chunk * NCW + (t + 1) * BT) * 8;
            const uint32_t dstb = smb + SM_B + (buf ^ 1) * 18432;
            #pragma unroll
            for (int r = 0; r < 4; r++) {
                int idx = r * 256 + tid, n = idx >> 3, kq = idx & 7;
                cp16(dstb + n * 144 + kq * 16, src + idx);
            }
            if (tid < 128)
                cp4(smb + SM_BIAS + (buf ^ 1) * 512 + tid * 4,
                    g_bias + chunk * NCW + (t + 1) * BT + tid);
            CP_COMMIT();
        }

        const uint32_t bbase = smb + SM_B + buf * 18432 + laneOffB;
        const float* biasb = sBias + buf * 128;

        #pragma unroll
        for (int ss = 0; ss < 2; ss++) {
            const int s = ng * 2 + ss;
            float d[2][4][4];
            #pragma unroll
            for (int j = 0; j < 4; j++) {
                float2 bp = *reinterpret_cast<const float2*>(
                    biasb + s * 32 + j * 8 + tidg * 2);
                #pragma unroll
                for (int mb = 0; mb < 2; mb++) {
                    d[mb][j][0] = bp.x; d[mb][j][1] = bp.y;
                    d[mb][j][2] = bp.x; d[mb][j][3] = bp.y;
                }
            }
            #pragma unroll
            for (int kt = 0; kt < 4; kt++) {
                uint32_t b0, b1, b2, b3, b4, b5, b6, b7;
                uint32_t ad = bbase + s * (32 * 144) + kt * 32;
                ldsm4(b0, b1, b2, b3, ad);
                ldsm4(b4, b5, b6, b7, ad + 16 * 144);
                #pragma unroll
                for (int mb = 0; mb < 2; mb++) {
                    mma16816(d[mb][0], aF[mb][kt], b0, b2);   // n  0- 7
                    mma16816(d[mb][1], aF[mb][kt], b1, b3);   // n  8-15
                    mma16816(d[mb][2], aF[mb][kt], b4, b6);   // n 16-23
                    mma16816(d[mb][3], aF[mb][kt], b5, b7);   // n 24-31
                }
            }
            // per-score top-2 update + subtile max
            const int nb0 = t * 128 + s * 32 + tidg * 2;
            #pragma unroll
            for (int mb = 0; mb < 2; mb++) {
                #pragma unroll
                for (int j = 0; j < 4; j++) {
                    const int n0 = nb0 + j * 8;
                    upd2(t1v[mb*2],   t1i[mb*2],   t2v[mb*2],   d[mb][j][0], n0);
                    upd2(t1v[mb*2],   t1i[mb*2],   t2v[mb*2],   d[mb][j][1], n0+1);
                    upd2(t1v[mb*2+1], t1i[mb*2+1], t2v[mb*2+1], d[mb][j][2], n0);
                    upd2(t1v[mb*2+1], t1i[mb*2+1], t2v[mb*2+1], d[mb][j][3], n0+1);
                }
                float r0m = fmaxf(fmaxf(d[mb][0][0], d[mb][0][1]),
                                  fmaxf(d[mb][1][0], d[mb][1][1]));
                r0m = fmaxf(r0m, fmaxf(fmaxf(d[mb][2][0], d[mb][2][1]),
                                       fmaxf(d[mb][3][0], d[mb][3][1])));
                float r1m = fmaxf(fmaxf(d[mb][0][2], d[mb][0][3]),
                                  fmaxf(d[mb][1][2], d[mb][1][3]));
                r1m = fmaxf(r1m, fmaxf(fmaxf(d[mb][2][2], d[mb][2][3]),
                                       fmaxf(d[mb][3][2], d[mb][3][3])));
                r0m = fmaxf(r0m, __shfl_xor_sync(0xffffffffu, r0m, 1));
                r0m = fmaxf(r0m, __shfl_xor_sync(0xffffffffu, r0m, 2));
                r1m = fmaxf(r1m, __shfl_xor_sync(0xffffffffu, r1m, 1));
                r1m = fmaxf(r1m, __shfl_xor_sync(0xffffffffu, r1m, 2));
                if (tidg == 0) {
                    const int sg  = t * 4 + s;
                    const int row = mg * 32 + mb * 16 + gid;
                    sMax[sg * 128 + row]     = r0m;
                    sMax[sg * 128 + row + 8] = r1m;
                }
            }
        }
        CP_WAIT0();
        __syncthreads();
    }

    // ---- cross-lane/warp top-2 merge ----
    uint32_t* wl    = reinterpret_cast<uint32_t*>(sm + SM_WL);
    ull*      sBest = reinterpret_cast<ull*>(sm + SM_BEST);
    uint32_t* wcnt  = reinterpret_cast<uint32_t*>(sm + SM_WCNT);
    if (tid == 0) *wcnt = 0;

    #pragma unroll
    for (int sl = 0; sl < 4; sl++) {
        float av = t1v[sl], a2 = t2v[sl]; int ai = t1i[sl];
        #pragma unroll
        for (int off = 1; off <= 2; off <<= 1) {
            float bv = __shfl_xor_sync(0xffffffffu, av, off);
            int   bi = __shfl_xor_sync(0xffffffffu, ai, off);
            float b2 = __shfl_xor_sync(0xffffffffu, a2, off);
            if (bv > av) { a2 = fmaxf(av, b2); av = bv; ai = bi; }
            else         { a2 = fmaxf(a2, bv); }
        }
        if (tidg == 0) {
            const int row = mg * 32 + (sl >> 1) * 16 + gid + (sl & 1) * 8;
            sT1[ng * 128 + row] = av;
            sT2[ng * 128 + row] = a2;
            sTI[ng * 128 + row] = ai;
        }
    }
    __syncthreads();

    // ---- classify tokens: proven winner vs ambiguous (needs exact rescue) ----
    if (tid < 128) {
        float av = sT1[tid],       a2 = sT2[tid];       int ai = sTI[tid];
        float bv = sT1[128 + tid], b2 = sT2[128 + tid]; int bi = sTI[128 + tid];
        float gt1, gt2; int gti;
        if (bv > av) { gt1 = bv; gti = bi; gt2 = fmaxf(av, b2); }
        else         { gt1 = av; gti = ai; gt2 = fmaxf(a2, bv); }
        const float thr2 = sEps[tid];
        if (gt1 - gt2 > thr2) {
            sBest[tid] = (ull)(uint32_t)gti;      // proven exact winner
        } else {
            sBest[tid] = ~0ull;
            const float cth = gt1 - thr2;
            for (int s2 = 0; s2 < 64; s2++)
                if (sMax[s2 * 128 + tid] >= cth) {
                    uint32_t p = atomicAdd(wcnt, 1u);
                    wl[p] = ((uint32_t)tid << 8) | (uint32_t)s2;
                }
        }
    }
    __syncthreads();

    // ---- exact fp32 rescue (rare; R1-identical arithmetic) ----
    const int cnt = *wcnt;
    const float* cqc = g_cbsq + chunk * NCW;
    for (int it = w; it < cnt; it += 8) {
        const uint32_t item = wl[it];
        const int tk = item >> 8, st = item & 255;
        const int n = st * 32 + lane;
        const float4* cp = reinterpret_cast<const float4*>(cbc + (size_t)n * SUB);
        const float4* xv = reinterpret_cast<const float4*>(
            x + (size_t)(t0 + tk) * DIM + chunk * SUB);
        float acc = 0.f;
        #pragma unroll
        for (int q = 0; q < 16; q++) {
            float4 c4 = __ldg(cp + q);
            float4 x4 = xv[q];
            acc = fmaf(c4.x, x4.x, acc);
            acc = fmaf(c4.y, x4.y, acc);
            acc = fmaf(c4.z, x4.z, acc);
            acc = fmaf(c4.w, x4.w, acc);
        }
        const float d2 = fmaf(-2.f, acc, sXsq[tk]) + __ldg(&cqc[n]);
        const ull key = ((ull)ord_f32(d2) << 32) | (uint32_t)n;
        atomicMin(&sBest[tk], key);
    }
    __syncthreads();

    // ---- gather winning codewords ----
    {
        const int r = tid >> 1, h = tid & 1;
        const uint32_t n = (uint32_t)(sBest[r] & 0xFFFFFFFFull);
        const float4* src = reinterpret_cast<const float4*>(
            cbc + (size_t)n * SUB + h * 32);
        float4* dst = reinterpret_cast<float4*>(
            out + (size_t)(t0 + r) * DIM + chunk * SUB + h * 32);
        #pragma unroll
        for (int q = 0; q < 8; q++) dst[q] = src[q];
    }
}

extern "C" void kernel_launch(void* const* d_in, const int* in_sizes, int n_in,
                              void* d_out, int out_size) {
    (void)n_in; (void)out_size;
    const float* x  = (const float*)d_in[0];   // (4,2048,1024) fp32
    const float* cb = (const float*)d_in[1];   // (16,2048,64) fp32
    float* out = (float*)d_out;
    const int tokens = in_sizes[0] / DIM;      // 8192

    cudaFuncSetAttribute(vq_kernel,
                         cudaFuncAttributeMaxDynamicSharedMemorySize, SM_TOTAL);

    prep_kernel<<<C_CHUNKS * NCW / 256, 256>>>(cb);
    cmax_kernel<<<C_CHUNKS, 256>>>(cb);
    dim3 grid(tokens / TM, C_CHUNKS);
    vq_kernel<<<grid, 256, SM_TOTAL>>>(x, cb, out);
}